// round 16
// baseline (speedup 1.0000x reference)
#include <cuda_runtime.h>
#include <math.h>

#define B_    8
#define C_    63
#define S_    2048
#define F_    5
#define E_    315
#define L1_   1023
#define L2_   511
#define L3_   255
#define EPG_  504
#define G_    (B_*L1_)
#define NE_   ((long)G_*EPG_)
#define NEG_INF (-3.402823466e38f)
#define ACC_BIAS 128.0f

typedef unsigned long long ull;

constexpr long SZ_X1 = (long)B_*L1_*E_;
constexpr long SZ_X2 = (long)B_*L2_*E_;
constexpr long SZ_X3 = (long)B_*L3_*E_;
constexpr long OFF_X1     = 0;
constexpr long OFF_X1PO   = OFF_X1   + SZ_X1;
constexpr long OFF_X2     = OFF_X1PO + SZ_X1;
constexpr long OFF_X2PO   = OFF_X2   + SZ_X2;
constexpr long OFF_X3     = OFF_X2PO + SZ_X2;
constexpr long OFF_POS2   = OFF_X3   + SZ_X3;
constexpr long OFF_POS3   = OFF_POS2 + (long)L2_*C_;
constexpr long OFF_Q1     = OFF_POS3 + (long)L3_*C_;
constexpr long OFF_KV1    = OFF_Q1   + (long)B_*L2_*E_;
constexpr long OFF_P1     = OFF_KV1  + (long)B_*L3_*2*E_;
constexpr long OFF_O1     = OFF_P1   + (long)B_*3*L2_*L3_;
constexpr long OFF_X2A    = OFF_O1   + (long)B_*L2_*E_;
constexpr long OFF_Q2     = OFF_X2A  + (long)B_*L2_*E_;
constexpr long OFF_KV2    = OFF_Q2   + (long)B_*L1_*E_;
constexpr long OFF_P2     = OFF_KV2  + (long)B_*L2_*2*E_;
constexpr long OFF_O2     = OFF_P2   + (long)B_*3*L1_*L2_;
constexpr long OFF_X1A    = OFF_O2   + (long)B_*L1_*E_;
constexpr long OFF_XGRAPH = OFF_X1A  + (long)B_*L1_*E_;
constexpr long OFF_XGATES = OFF_XGRAPH + (long)G_*32;
constexpr long OFF_GRUOUT = OFF_XGATES + (long)G_*192;
constexpr long OFF_SCORES = OFF_GRUOUT + (long)G_*64;
constexpr long SCRATCH_TOTAL = OFF_SCORES + (long)G_*3;

__device__ float g_scratch[SCRATCH_TOTAL];

// ============ double-single (ds) fp32 library ============
struct dsf { float h, l; };
__device__ __forceinline__ dsf ds_two_sum(float a, float b) {
    float s = __fadd_rn(a, b);
    float bb = __fsub_rn(s, a);
    float err = __fadd_rn(__fsub_rn(a, __fsub_rn(s, bb)), __fsub_rn(b, bb));
    return {s, err};
}
__device__ __forceinline__ dsf ds_quick(float a, float b) {
    float s = __fadd_rn(a, b);
    return {s, __fsub_rn(b, __fsub_rn(s, a))};
}
__device__ __forceinline__ dsf ds_neg(dsf x) { return {-x.h, -x.l}; }
__device__ __forceinline__ dsf ds_add(dsf x, dsf y) {
    dsf t = ds_two_sum(x.h, y.h);
    t.l = __fadd_rn(t.l, __fadd_rn(x.l, y.l));
    return ds_quick(t.h, t.l);
}
__device__ __forceinline__ dsf ds_add_f(dsf x, float f) {
    dsf t = ds_two_sum(x.h, f);
    t.l = __fadd_rn(t.l, x.l);
    return ds_quick(t.h, t.l);
}
__device__ __forceinline__ dsf ds_mul(dsf x, dsf y) {
    float p = __fmul_rn(x.h, y.h);
    float e = __fmaf_rn(x.h, y.h, -p);
    e = __fmaf_rn(x.h, y.l, e);
    e = __fmaf_rn(x.l, y.h, e);
    return ds_quick(p, e);
}
__device__ __forceinline__ dsf ds_mul_f(dsf x, float f) {
    float p = __fmul_rn(x.h, f);
    float e = __fmaf_rn(x.h, f, -p);
    e = __fmaf_rn(x.l, f, e);
    return ds_quick(p, e);
}
__device__ __forceinline__ dsf ds_prod(float a, float b) {
    float p = __fmul_rn(a, b);
    return {p, __fmaf_rn(a, b, -p)};
}
__device__ __forceinline__ dsf ds_recip(dsf y) {
    float r0 = __frcp_rn(y.h);
    dsf om = ds_add_f(ds_neg(ds_mul_f(y, r0)), 1.0f);
    return ds_add_f(ds_mul_f(om, r0), r0);
}
__device__ __forceinline__ dsf ds_recip_f(float f) {
    float r0 = __frcp_rn(f);
    float t = __fmaf_rn(-f, r0, 1.0f);
    return ds_quick(r0, __fmul_rn(r0, t));
}
__device__ __forceinline__ void ds_mac_dsw(dsf& acc, float w, float hh, float hl) {
    float p = __fmul_rn(w, hh);
    float e = __fmaf_rn(w, hh, -p);
    e = __fmaf_rn(w, hl, e);
    dsf t = ds_two_sum(acc.h, p);
    acc.h = t.h;
    acc.l = __fadd_rn(acc.l, __fadd_rn(t.l, e));
}
__device__ __forceinline__ void ds_macf(dsf& acc, float a, float b) {
    float p = __fmul_rn(a, b);
    float e = __fmaf_rn(a, b, -p);
    dsf t = ds_two_sum(acc.h, p);
    acc.h = t.h;
    acc.l = __fadd_rn(acc.l, __fadd_rn(t.l, e));
}
constexpr double LN2D = 0.6931471805599453094172321214581766;
constexpr float EXP_C1 = 0.693359375f;
constexpr float EXP_C2 = (float)(LN2D - (double)EXP_C1);
constexpr float EXP_C3 = (float)(LN2D - (double)EXP_C1 - (double)EXP_C2);
constexpr float L2EF = 1.4426950408889634f;
constexpr float C6H = (float)(1.0/6.0),  C6L = (float)(1.0/6.0 - (double)C6H);
constexpr float C24H = (float)(1.0/24.0), C24L = (float)(1.0/24.0 - (double)C24H);
constexpr float I63H = (float)(1.0/63.0), I63L = (float)(1.0/63.0 - (double)I63H);
constexpr double ISCD = 0.09759000729485331905;
constexpr float ISCH = (float)ISCD, ISCL = (float)(ISCD - (double)ISCH);

__device__ __forceinline__ dsf ds_exp(dsf x) {
    if (x.h < -86.0f) return {0.f, 0.f};
    if (x.h >  86.0f) return {1e37f, 0.f};
    float nf = rintf(__fmul_rn(x.h, L2EF));
    float t1 = __fmaf_rn(-nf, EXP_C1, x.h);
    dsf p2 = ds_prod(nf, EXP_C2);
    dsf r = ds_two_sum(t1, -p2.h);
    r.l = __fadd_rn(r.l, __fadd_rn(x.l, __fadd_rn(-p2.l, __fmul_rn(-nf, EXP_C3))));
    r = ds_quick(r.h, r.l);
    dsf r2 = ds_mul(r, r);
    dsf r3 = ds_mul(r2, r);
    dsf r4 = ds_mul(r2, r2);
    float rf = r.h;
    float tail = __fmaf_rn(rf, 2.7557319e-7f, 2.7557319e-6f);
    tail = __fmaf_rn(rf, tail, 2.4801587e-5f);
    tail = __fmaf_rn(rf, tail, 1.9841270e-4f);
    tail = __fmaf_rn(rf, tail, 1.3888889e-3f);
    tail = __fmaf_rn(rf, tail, 8.3333333e-3f);
    float q = __fmul_rn(__fmul_rn(r4.h, rf), tail);
    dsf acc = ds_add(r, ds_mul_f(r2, 0.5f));
    acc = ds_add(acc, ds_mul(r3, dsf{C6H, C6L}));
    acc = ds_add(acc, ds_mul(r4, dsf{C24H, C24L}));
    acc = ds_add_f(acc, q);
    acc = ds_add_f(acc, 1.0f);
    float sc = __int_as_float(((int)nf + 127) << 23);
    return {__fmul_rn(acc.h, sc), __fmul_rn(acc.l, sc)};
}
__device__ __forceinline__ dsf ds_sigmoid(dsf x) {
    return ds_recip(ds_add_f(ds_exp(ds_neg(x)), 1.0f));
}
__device__ __forceinline__ dsf ds_tanh(dsf x) {
    dsf e = ds_exp(dsf{__fmul_rn(x.h, 2.f), __fmul_rn(x.l, 2.f)});
    return ds_mul(ds_add_f(e, -1.0f), ds_recip(ds_add_f(e, 1.0f)));
}

// ---------- packed f32x2 ----------
__device__ __forceinline__ ull f2x2_add(ull a, ull b) {
    ull r; asm("add.rn.f32x2 %0, %1, %2;" : "=l"(r) : "l"(a), "l"(b)); return r;
}
__device__ __forceinline__ ull f2x2_sub(ull a, ull b) {
    ull r; asm("sub.rn.f32x2 %0, %1, %2;" : "=l"(r) : "l"(a), "l"(b)); return r;
}
__device__ __forceinline__ ull f2x2_mul(ull a, ull b) {
    ull r; asm("mul.rn.f32x2 %0, %1, %2;" : "=l"(r) : "l"(a), "l"(b)); return r;
}
__device__ __forceinline__ ull f2x2_fma(ull a, ull b, ull c) {
    ull r; asm("fma.rn.f32x2 %0, %1, %2, %3;" : "=l"(r) : "l"(a), "l"(b), "l"(c)); return r;
}
__device__ __forceinline__ ull f2x2_neg(ull a) { return a ^ 0x8000000080000000ull; }
__device__ __forceinline__ ull f2x2_splat(float x) {
    ull r; asm("mov.b64 %0, {%1, %1};" : "=l"(r) : "f"(x)); return r;
}
__device__ __forceinline__ void f2x2_unpack(ull v, float& x, float& y) {
    asm("mov.b64 {%0, %1}, %2;" : "=f"(x), "=f"(y) : "l"(v));
}
// biased Fast2Sum ds MAC (hi pre-biased); nb = -b precomputed.
// em = fma(a, -b, p) = p - a*b = -(exact residual). 7 packed ops / 2 MACs.
__device__ __forceinline__ void dsmac2(ull a, ull b, ull nb, ull& hi, ull& lo) {
    ull p   = f2x2_mul(a, b);
    ull em  = f2x2_fma(a, nb, p);
    ull s   = f2x2_add(hi, p);
    ull z   = f2x2_sub(s, hi);
    ull err = f2x2_sub(p, z);
    hi = s;
    lo = f2x2_add(lo, f2x2_sub(err, em));
}
__device__ __forceinline__ void dsmac2_dsh(ull w, ull nw, ull hh, ull hl, ull& hi, ull& lo) {
    ull p   = f2x2_mul(w, hh);
    ull em  = f2x2_fma(nw, hh, p);
    ull s   = f2x2_add(hi, p);
    ull z   = f2x2_sub(s, hi);
    ull err = f2x2_sub(p, z);
    hi = s;
    lo = f2x2_add(lo, f2x2_add(f2x2_sub(err, em), f2x2_mul(w, hl)));
}

// -------- adaptive avg pool --------
__global__ void pool_k(const float* __restrict__ in, float* __restrict__ out,
                       int Lin, int Lout) {
    int idx = blockIdx.x * blockDim.x + threadIdx.x;
    if (idx >= Lout * C_) return;
    int i = idx / C_, c = idx - C_ * i;
    int s = (i * Lin) / Lout;
    int e = ((i + 1) * Lin + Lout - 1) / Lout;
    double acc = 0.0;
    for (int l = s; l < e; l++) acc += (double)in[l * C_ + c];
    out[idx] = (float)(acc / (double)(e - s));
}

// -------- conv df64 + fused pos --------
__global__ __launch_bounds__(256, 3) void conv_k(
    const float* __restrict__ in, const float* __restrict__ W,
    const float* __restrict__ bias, const float* __restrict__ pos,
    float* __restrict__ outPre, float* __restrict__ outPost,
    int Lin, int Lout, int inOrig) {
    int l0 = blockIdx.x * 64;
    int bf = blockIdx.y;
    int b = bf / F_, f = bf - b * F_;
    __shared__ __align__(16) float As[2][16][68];
    __shared__ __align__(16) float Bs[2][16][68];
    int tid = threadIdx.x;
    int tx = tid & 15, ty = tid >> 4;
    const ull bias2 = f2x2_splat(ACC_BIAS);
    ull hi2[4][2], lo2[4][2];
#pragma unroll
    for (int i = 0; i < 4; i++)
#pragma unroll
        for (int jp = 0; jp < 2; jp++) { hi2[i][jp] = bias2; lo2[i][jp] = 0ull; }
    const int akk = tid & 15, amb = tid >> 4;
    const int bn = tid & 63, bkb = tid >> 6;
    float ra[4], rb[4];
    auto loadA = [&](int k0) {
        int kidx = k0 + akk;
#pragma unroll
        for (int q = 0; q < 4; q++) {
            int co = amb + q * 16;
            ra[q] = (co < 63 && kidx < 189) ? W[co * 189 + kidx] : 0.f;
        }
    };
    auto loadB = [&](int k0) {
        int gl = l0 + bn;
#pragma unroll
        for (int q = 0; q < 4; q++) {
            int kidx = k0 + bkb + q * 4;
            float v = 0.f;
            if (kidx < 189 && gl < Lout) {
                int ci = kidx / 3, kx = kidx - ci * 3;
                int si = 2 * gl + kx;
                v = inOrig ? in[((long)(b * 63 + ci) * Lin + si) * 5 + f]
                           : in[((long)b * Lin + si) * 315 + f * 63 + ci];
            }
            rb[q] = v;
        }
    };
    loadA(0); loadB(0);
    int buf = 0;
    for (int k0 = 0; k0 < 192; k0 += 16) {
#pragma unroll
        for (int q = 0; q < 4; q++) As[buf][akk][amb + q * 16] = ra[q];
#pragma unroll
        for (int q = 0; q < 4; q++) Bs[buf][bkb + q * 4][bn] = rb[q];
        __syncthreads();
        if (k0 + 16 < 192) { loadA(k0 + 16); loadB(k0 + 16); }
#pragma unroll
        for (int kk = 0; kk < 16; kk++) {
            float4 a4 = *(const float4*)&As[buf][kk][ty * 4];
            ulonglong2 bq = *(const ulonglong2*)&Bs[buf][kk][tx * 4];
            ull b2[2] = {bq.x, bq.y};
            ull nb2[2] = {f2x2_neg(bq.x), f2x2_neg(bq.y)};
            ull a2[4] = {f2x2_splat(a4.x), f2x2_splat(a4.y),
                         f2x2_splat(a4.z), f2x2_splat(a4.w)};
#pragma unroll
            for (int i = 0; i < 4; i++)
#pragma unroll
                for (int jp = 0; jp < 2; jp++)
                    dsmac2(a2[i], b2[jp], nb2[jp], hi2[i][jp], lo2[i][jp]);
        }
        buf ^= 1;
        __syncthreads();
    }
#pragma unroll
    for (int i = 0; i < 4; i++) {
        int co = ty * 4 + i;
        if (co >= 63) continue;
#pragma unroll
        for (int jp = 0; jp < 2; jp++) {
            float h0, h1, l0f, l1f;
            f2x2_unpack(hi2[i][jp], h0, h1);
            f2x2_unpack(lo2[i][jp], l0f, l1f);
            float hv[2] = {__fsub_rn(h0, ACC_BIAS), __fsub_rn(h1, ACC_BIAS)};
            float lv[2] = {l0f, l1f};
#pragma unroll
            for (int u = 0; u < 2; u++) {
                int l = l0 + tx * 4 + jp * 2 + u;
                if (l >= Lout) continue;
                dsf sum = ds_two_sum(hv[u], lv[u]);
                float vpre = ds_add_f(sum, bias[co]).h;
                long oidx = ((long)b * Lout + l) * 315 + f * 63 + co;
                if (outPre)  outPre[oidx] = vpre;
                if (outPost) outPost[oidx] = __fadd_rn(vpre, pos[l * 63 + co]);
            }
        }
    }
}

// -------- generic GEMM df64, 64x64 tile, 4 CTAs/SM target --------
__global__ __launch_bounds__(256, 4) void gemm_k(
    const float* __restrict__ A, int lda, long sAo, long sAi,
    const float* __restrict__ Bm, int ldb, long sBo, long sBi,
    float* __restrict__ Cm, int ldc, long sCo, long sCi,
    const float* __restrict__ bias,
    int M, int N, int K, int scaleIsc, int transB, int nInner) {
    int z = blockIdx.z;
    int zo = z / nInner, zi = z - zo * nInner;
    A += zo * sAo + zi * sAi;
    Bm += zo * sBo + zi * sBi;
    Cm += zo * sCo + zi * sCi;
    __shared__ __align__(16) float As[2][16][68];
    __shared__ __align__(16) float Bs[2][16][68];
    int m0 = blockIdx.y * 64, n0 = blockIdx.x * 64;
    int tid = threadIdx.x;
    int tx = tid & 15, ty = tid >> 4;
    const ull bias2 = f2x2_splat(ACC_BIAS);
    ull hi2[4][2], lo2[4][2];
#pragma unroll
    for (int i = 0; i < 4; i++)
#pragma unroll
        for (int jp = 0; jp < 2; jp++) { hi2[i][jp] = bias2; lo2[i][jp] = 0ull; }
    const int akk = tid & 15, amb = tid >> 4;
    const int bn = tid & 63, bkb = tid >> 6;
    float ra[4], rb[4];
    auto loadA = [&](int k0) {
        int gk = k0 + akk;
        bool kok = gk < K;
#pragma unroll
        for (int q = 0; q < 4; q++) {
            int gm = m0 + amb + q * 16;
            ra[q] = (gm < M && kok) ? A[(long)gm * lda + gk] : 0.f;
        }
    };
    auto loadB = [&](int k0) {
        if (transB) {
            int gk = k0 + akk;
            bool kok = gk < K;
#pragma unroll
            for (int q = 0; q < 4; q++) {
                int gn = n0 + amb + q * 16;
                rb[q] = (gn < N && kok) ? Bm[(long)gn * ldb + gk] : 0.f;
            }
        } else {
            int gn = n0 + bn;
            bool nok = gn < N;
#pragma unroll
            for (int q = 0; q < 4; q++) {
                int gk = k0 + bkb + q * 4;
                rb[q] = (nok && gk < K) ? Bm[(long)gk * ldb + gn] : 0.f;
            }
        }
    };
    loadA(0); loadB(0);
    int buf = 0;
    for (int k0 = 0; k0 < K; k0 += 16) {
#pragma unroll
        for (int q = 0; q < 4; q++) As[buf][akk][amb + q * 16] = ra[q];
        if (transB) {
#pragma unroll
            for (int q = 0; q < 4; q++) Bs[buf][akk][amb + q * 16] = rb[q];
        } else {
#pragma unroll
            for (int q = 0; q < 4; q++) Bs[buf][bkb + q * 4][bn] = rb[q];
        }
        __syncthreads();
        if (k0 + 16 < K) { loadA(k0 + 16); loadB(k0 + 16); }
#pragma unroll
        for (int kk = 0; kk < 16; kk++) {
            float4 a4 = *(const float4*)&As[buf][kk][ty * 4];
            ulonglong2 bq = *(const ulonglong2*)&Bs[buf][kk][tx * 4];
            ull b2[2] = {bq.x, bq.y};
            ull nb2[2] = {f2x2_neg(bq.x), f2x2_neg(bq.y)};
            ull a2[4] = {f2x2_splat(a4.x), f2x2_splat(a4.y),
                         f2x2_splat(a4.z), f2x2_splat(a4.w)};
#pragma unroll
            for (int i = 0; i < 4; i++)
#pragma unroll
                for (int jp = 0; jp < 2; jp++)
                    dsmac2(a2[i], b2[jp], nb2[jp], hi2[i][jp], lo2[i][jp]);
        }
        buf ^= 1;
        __syncthreads();
    }
#pragma unroll
    for (int i = 0; i < 4; i++) {
        int gm = m0 + ty * 4 + i;
        if (gm >= M) continue;
#pragma unroll
        for (int jp = 0; jp < 2; jp++) {
            float h0, h1, l0f, l1f;
            f2x2_unpack(hi2[i][jp], h0, h1);
            f2x2_unpack(lo2[i][jp], l0f, l1f);
            float hv[2] = {__fsub_rn(h0, ACC_BIAS), __fsub_rn(h1, ACC_BIAS)};
            float lv[2] = {l0f, l1f};
#pragma unroll
            for (int u = 0; u < 2; u++) {
                int gn = n0 + tx * 4 + jp * 2 + u;
                if (gn >= N) continue;
                dsf v = ds_two_sum(hv[u], lv[u]);
                if (scaleIsc) v = ds_mul(v, dsf{ISCH, ISCL});
                if (bias) v = ds_add_f(v, bias[gn]);
                Cm[(long)gm * ldc + gn] = v.h;
            }
        }
    }
}

// -------- softmax, ds exp --------
__global__ void softmax_k(float* __restrict__ P, int rows, int Ld) {
    int warp = (blockIdx.x * blockDim.x + threadIdx.x) >> 5;
    int lane = threadIdx.x & 31;
    if (warp >= rows) return;
    float* p = P + (long)warp * Ld;
    float v[16];
    float m = NEG_INF;
#pragma unroll
    for (int q = 0; q < 16; q++) {
        int i = lane + (q << 5);
        v[q] = (i < Ld) ? p[i] : NEG_INF;
        m = fmaxf(m, v[q]);
    }
#pragma unroll
    for (int off = 16; off; off >>= 1) m = fmaxf(m, __shfl_xor_sync(0xffffffffu, m, off));
    dsf ex[16];
    dsf s = {0.f, 0.f};
#pragma unroll
    for (int q = 0; q < 16; q++) {
        int i = lane + (q << 5);
        ex[q] = (i < Ld) ? ds_exp(ds_two_sum(v[q], -m)) : dsf{0.f, 0.f};
        s = ds_add(s, ex[q]);
    }
#pragma unroll
    for (int off = 16; off; off >>= 1) {
        dsf o = {__shfl_xor_sync(0xffffffffu, s.h, off),
                 __shfl_xor_sync(0xffffffffu, s.l, off)};
        s = ds_add(s, o);
    }
    dsf inv = ds_recip(s);
#pragma unroll
    for (int q = 0; q < 16; q++) {
        int i = lane + (q << 5);
        if (i < Ld) p[i] = ds_mul(ex[q], inv).h;
    }
}

// -------- GATv2 per graph: thread-per-slot scores, warp-per-dst combine --------
__global__ __launch_bounds__(256) void gat_k(
    const float* __restrict__ xfeat, const int* __restrict__ edge_index,
    const float* __restrict__ edge_attr,
    const float* __restrict__ wl, const float* __restrict__ blv,
    const float* __restrict__ wr, const float* __restrict__ brv,
    const float* __restrict__ wev, const float* __restrict__ attv,
    const float* __restrict__ gbias, float* __restrict__ xgraph) {
    int g = blockIdx.x;
    int tid = threadIdx.x;
    int warp = tid >> 5, lane = tid & 31;
    __shared__ float xn[E_];
    __shared__ float xl[63 * 33], xr[63 * 33];
    __shared__ float eav[EPG_];
    __shared__ short srcl[EPG_], dstl[EPG_], sorted_[EPG_];
    __shared__ int deg[63], start_[64], fill[63];
    __shared__ float lah[63], lal[63];
    __shared__ float sch[EPG_ + 63], scl[EPG_ + 63];
    __shared__ float2 outrow[2016];
    __shared__ float wls[160], wrs[160], wes[32], atts[32];

    const long ebase = (long)g * EPG_;
    for (int i = tid; i < E_; i += 256) xn[i] = xfeat[(long)g * E_ + i];
    if (tid < 160) { wls[tid] = wl[tid]; wrs[tid] = wr[tid]; }
    if (tid < 32)  { wes[tid] = wev[tid]; atts[tid] = attv[tid]; }
    if (tid < 63)  { deg[tid] = 0; fill[tid] = 0; }
    for (int e = tid; e < EPG_; e += 256) {
        srcl[e] = (short)(edge_index[ebase + e] - g * 63);
        dstl[e] = (short)(edge_index[NE_ + ebase + e] - g * 63);
        eav[e]  = edge_attr[ebase + e];
    }
    __syncthreads();
    for (int i = tid; i < 2016; i += 256) {
        int nd = i >> 5, k = i & 31;
        const float* xv = &xn[nd * 5];
        dsf sl = {blv[k], 0.f}, sr = {brv[k], 0.f};
#pragma unroll
        for (int f = 0; f < 5; f++) {
            ds_macf(sl, wls[k * 5 + f], xv[f]);
            ds_macf(sr, wrs[k * 5 + f], xv[f]);
        }
        xl[nd * 33 + k] = __fadd_rn(sl.h, sl.l);
        xr[nd * 33 + k] = __fadd_rn(sr.h, sr.l);
    }
    for (int e = tid; e < EPG_; e += 256) atomicAdd(&deg[dstl[e]], 1);
    __syncthreads();
    if (tid == 0) {
        int a = 0;
        for (int d = 0; d < 63; d++) { start_[d] = a; a += deg[d]; }
        start_[63] = a;
    }
    __syncthreads();
    for (int e = tid; e < EPG_; e += 256) {
        int d = dstl[e];
        int p = start_[d] + atomicAdd(&fill[d], 1);
        sorted_[p] = (short)e;
    }
    __syncthreads();
    if (tid < 63) {
        int s0 = start_[tid], cnt = deg[tid];
        dsf la = {0.f, 0.f};
        for (int j = 0; j < cnt; j++) la = ds_add_f(la, eav[sorted_[s0 + j]]);
        la = ds_mul(la, ds_recip_f((float)(cnt > 0 ? cnt : 1)));
        lah[tid] = la.h; lal[tid] = la.l;
    }
    __syncthreads();
    for (int i = tid; i < EPG_ + 63; i += 256) {
        int src, d;
        dsf sco = {0.f, 0.f};
        if (i < EPG_) {
            int e = sorted_[i];
            src = srcl[e]; d = dstl[e];
            float ea = eav[e];
#pragma unroll
            for (int k = 0; k < 32; k++) {
                dsf m = ds_add(ds_two_sum(xl[src * 33 + k], xr[d * 33 + k]),
                               ds_prod(wes[k], ea));
                if (m.h < 0.f) m = ds_mul_f(m, 0.2f);
                ds_mac_dsw(sco, atts[k], m.h, m.l);
            }
        } else {
            d = i - EPG_; src = d;
            dsf la = {lah[d], lal[d]};
#pragma unroll
            for (int k = 0; k < 32; k++) {
                dsf m = ds_add(ds_two_sum(xl[d * 33 + k], xr[d * 33 + k]),
                               ds_mul_f(la, wes[k]));
                if (m.h < 0.f) m = ds_mul_f(m, 0.2f);
                ds_mac_dsw(sco, atts[k], m.h, m.l);
            }
        }
        dsf sn = ds_two_sum(sco.h, sco.l);
        sch[i] = sn.h; scl[i] = sn.l;
    }
    __syncthreads();
    for (int d = warp; d < 63; d += 8) {
        int s0 = start_[d];
        int cnt = deg[d];
        dsf mx = {NEG_INF, 0.f};
        for (int j = lane; j <= cnt; j += 32) {
            int slot = (j < cnt) ? (s0 + j) : (EPG_ + d);
            dsf sv = {sch[slot], scl[slot]};
            if (sv.h > mx.h) mx = sv;
        }
#pragma unroll
        for (int off = 16; off; off >>= 1) {
            float oh = __shfl_xor_sync(0xffffffffu, mx.h, off);
            float ol = __shfl_xor_sync(0xffffffffu, mx.l, off);
            if (oh > mx.h) { mx.h = oh; mx.l = ol; }
        }
        dsf ssum = {0.f, 0.f};
        for (int j = lane; j <= cnt; j += 32) {
            int slot = (j < cnt) ? (s0 + j) : (EPG_ + d);
            dsf ex = ds_exp(ds_add(dsf{sch[slot], scl[slot]}, ds_neg(mx)));
            sch[slot] = ex.h; scl[slot] = ex.l;
            ssum = ds_add(ssum, ex);
        }
#pragma unroll
        for (int off = 16; off; off >>= 1) {
            dsf o = {__shfl_xor_sync(0xffffffffu, ssum.h, off),
                     __shfl_xor_sync(0xffffffffu, ssum.l, off)};
            ssum = ds_add(ssum, o);
        }
        __syncwarp();
        dsf acc = {0.f, 0.f};
        for (int j = 0; j <= cnt; j++) {
            int slot, src;
            if (j < cnt) { slot = s0 + j; src = srcl[sorted_[slot]]; }
            else { slot = EPG_ + d; src = d; }
            acc = ds_add(acc, ds_mul_f(dsf{sch[slot], scl[slot]}, xl[src * 33 + lane]));
        }
        dsf o = ds_mul(acc, ds_recip(ssum));
        outrow[d * 32 + lane] = make_float2(o.h, o.l);
        __syncwarp();
    }
    __syncthreads();
    if (tid < 32) {
        dsf s = {0.f, 0.f};
        for (int d = 0; d < 63; d++) {
            float2 v = outrow[d * 32 + tid];
            s = ds_add(s, dsf{v.x, v.y});
        }
        s = ds_mul(s, dsf{I63H, I63L});
        xgraph[(long)g * 32 + tid] = ds_add_f(s, gbias[tid]).h;
    }
}

// -------- GRU scan: 2 syncs/step, register-local r/z sigmoid --------
__global__ __launch_bounds__(192) void gru_k(
    const float* __restrict__ xgates, const float* __restrict__ whh,
    const float* __restrict__ bhh, float* __restrict__ gruout) {
    int b = blockIdx.x;
    int t = threadIdx.x;
    __shared__ __align__(8) float hsh[64], hsl[64];
    __shared__ float hgh[64], hgl[64];       // only gate-n rows (threads 128..191) need smem
    __shared__ float rzh[128], rzl[128];
    ull w2[32], nw2[32];
#pragma unroll
    for (int j = 0; j < 32; j++) {
        float w0 = whh[t * 64 + 2 * j], w1 = whh[t * 64 + 2 * j + 1];
        ull r; asm("mov.b64 %0, {%1, %2};" : "=l"(r) : "f"(w0), "f"(w1));
        w2[j] = r;
        nw2[j] = f2x2_neg(r);
    }
    float bh = bhh[t];
    const ull bias2 = f2x2_splat(ACC_BIAS);
    if (t < 64) { hsh[t] = 0.f; hsl[t] = 0.f; }
    __syncthreads();
    for (int l = 0; l < L1_; l++) {
        ull hiA = bias2, loA = 0ull, hiB = bias2, loB = 0ull;
#pragma unroll
        for (int j = 0; j < 32; j += 2) {
            ull hhA = *(const ull*)&hsh[2 * j];
            ull hlA = *(const ull*)&hsl[2 * j];
            dsmac2_dsh(w2[j], nw2[j], hhA, hlA, hiA, loA);
            ull hhB = *(const ull*)&hsh[2 * j + 2];
            ull hlB = *(const ull*)&hsl[2 * j + 2];
            dsmac2_dsh(w2[j + 1], nw2[j + 1], hhB, hlB, hiB, loB);
        }
        float a0, a1, b0, b1, c0, c1, d0, d1;
        f2x2_unpack(hiA, a0, a1); f2x2_unpack(loA, c0, c1);
        f2x2_unpack(hiB, b0, b1); f2x2_unpack(loB, d0, d1);
        a0 = __fsub_rn(a0, ACC_BIAS); a1 = __fsub_rn(a1, ACC_BIAS);
        b0 = __fsub_rn(b0, ACC_BIAS); b1 = __fsub_rn(b1, ACC_BIAS);
        dsf hg = ds_add(ds_add(dsf{a0, c0}, dsf{a1, c1}),
                        ds_add(dsf{b0, d0}, dsf{b1, d1}));
        hg = ds_add_f(hg, bh);
        const float* xg = xgates + ((long)b * L1_ + l) * 192;
        if (t < 128) {
            // own-thread hg: sigmoid immediately, no barrier needed
            dsf v = ds_sigmoid(ds_add_f(hg, xg[t]));
            rzh[t] = v.h; rzl[t] = v.l;
        } else {
            hgh[t - 128] = hg.h; hgl[t - 128] = hg.l;
        }
        __syncthreads();
        if (t < 64) {
            dsf r = {rzh[t], rzl[t]};
            dsf z = {rzh[64 + t], rzl[64 + t]};
            dsf n = ds_tanh(ds_add_f(ds_mul(r, dsf{hgh[t], hgl[t]}), xg[128 + t]));
            dsf h = {hsh[t], hsl[t]};
            dsf hnew = ds_add(ds_mul(ds_add_f(ds_neg(z), 1.0f), n), ds_mul(z, h));
            hsh[t] = hnew.h; hsl[t] = hnew.l;
            gruout[((long)b * L1_ + l) * 64 + t] = hnew.h;
        }
        __syncthreads();
    }
}

// -------- classifier --------
__global__ __launch_bounds__(256) void cls_k(
    const float* __restrict__ gru, const float* __restrict__ w1,
    const float* __restrict__ b1, const float* __restrict__ w2,
    const float* __restrict__ b2, float* __restrict__ sc) {
    __shared__ float s1[2048], s2[96], sb1[32], sb2[3];
    int t = threadIdx.x;
    for (int i = t; i < 2048; i += 256) s1[i] = w1[i];
    if (t < 96) s2[t] = w2[t];
    if (t < 32) sb1[t] = b1[t];
    if (t < 3)  sb2[t] = b2[t];
    __syncthreads();
    int g = blockIdx.x * 256 + t;
    if (g >= G_) return;
    float h[64];
    const float* gr = gru + (long)g * 64;
#pragma unroll
    for (int j = 0; j < 64; j++) h[j] = gr[j];
    dsf o0 = {sb2[0], 0.f}, o1 = {sb2[1], 0.f}, o2 = {sb2[2], 0.f};
    for (int u = 0; u < 32; u++) {
        dsf a = {sb1[u], 0.f};
#pragma unroll
        for (int j = 0; j < 64; j++) ds_macf(a, s1[u * 64 + j], h[j]);
        if (a.h < 0.f) { a.h = 0.f; a.l = 0.f; }
        ds_mac_dsw(o0, s2[u], a.h, a.l);
        ds_mac_dsw(o1, s2[32 + u], a.h, a.l);
        ds_mac_dsw(o2, s2[64 + u], a.h, a.l);
    }
    sc[(long)g * 3 + 0] = __fadd_rn(o0.h, o0.l);
    sc[(long)g * 3 + 1] = __fadd_rn(o1.h, o1.l);
    sc[(long)g * 3 + 2] = __fadd_rn(o2.h, o2.l);
}

// -------- top-5 --------
__global__ __launch_bounds__(128) void topk_k(const float* __restrict__ scores,
                                              float* __restrict__ out) {
    int bc = blockIdx.x;
    int b = bc / 3, c = bc - 3 * b;
    __shared__ float sv[L1_];
    __shared__ float bval[128];
    __shared__ int bidx[128];
    __shared__ float ssum;
    int t = threadIdx.x;
    for (int i = t; i < L1_; i += 128) sv[i] = scores[((long)b * L1_ + i) * 3 + c];
    if (t == 0) ssum = 0.f;
    __syncthreads();
    for (int k = 0; k < 5; k++) {
        float mv = NEG_INF; int mi = 0x7fffffff;
        for (int i = t; i < L1_; i += 128) {
            float v = sv[i];
            if (v > mv) { mv = v; mi = i; }
        }
        bval[t] = mv; bidx[t] = mi;
        __syncthreads();
        for (int off = 64; off; off >>= 1) {
            if (t < off) {
                if (bval[t + off] > bval[t] ||
                    (bval[t + off] == bval[t] && bidx[t + off] < bidx[t])) {
                    bval[t] = bval[t + off]; bidx[t] = bidx[t + off];
                }
            }
            __syncthreads();
        }
        if (t == 0) {
            out[24 + (b * 5 + k) * 3 + c] = (float)bidx[0];
            ssum += bval[0];
            sv[bidx[0]] = NEG_INF;
        }
        __syncthreads();
    }
    if (t == 0) out[b * 3 + c] = ssum * 0.2f;
}

extern "C" void kernel_launch(void* const* d_in, const int* in_sizes, int n_in,
                              void* d_out, int out_size) {
    const float* x        = (const float*)d_in[0];
    const float* c1w      = (const float*)d_in[1];
    const float* c1b      = (const float*)d_in[2];
    const float* c2w      = (const float*)d_in[3];
    const float* c2b      = (const float*)d_in[4];
    const float* c3w      = (const float*)d_in[5];
    const float* c3b      = (const float*)d_in[6];
    const float* pos_emb  = (const float*)d_in[7];
    const float* ain_w    = (const float*)d_in[8];
    const float* ain_b    = (const float*)d_in[9];
    const float* aout_w   = (const float*)d_in[10];
    const float* aout_b   = (const float*)d_in[11];
    const float* gat_wl   = (const float*)d_in[12];
    const float* gat_bl   = (const float*)d_in[13];
    const float* gat_wr   = (const float*)d_in[14];
    const float* gat_br   = (const float*)d_in[15];
    const float* gat_we   = (const float*)d_in[16];
    const float* gat_att  = (const float*)d_in[17];
    const float* gat_bias = (const float*)d_in[18];
    const float* gru_wih  = (const float*)d_in[19];
    const float* gru_whh  = (const float*)d_in[20];
    const float* gru_bih  = (const float*)d_in[21];
    const float* gru_bhh  = (const float*)d_in[22];
    const float* fc1_w    = (const float*)d_in[23];
    const float* fc1_b    = (const float*)d_in[24];
    const float* fc2_w    = (const float*)d_in[25];
    const float* fc2_b    = (const float*)d_in[26];
    const float* e_attr   = (const float*)d_in[27];
    const int*   e_index  = (const int*)d_in[28];
    float* out = (float*)d_out;

    float* s;
    cudaGetSymbolAddress((void**)&s, g_scratch);

    pool_k<<<(L2_ * C_ + 255) / 256, 256>>>(pos_emb, s + OFF_POS2, L1_, L2_);
    pool_k<<<(L3_ * C_ + 255) / 256, 256>>>(s + OFF_POS2, s + OFF_POS3, L2_, L3_);
    conv_k<<<dim3(16, 40), 256>>>(x, c1w, c1b, pos_emb,
                                  s + OFF_X1, s + OFF_X1PO, S_, L1_, 1);
    conv_k<<<dim3(8, 40), 256>>>(s + OFF_X1, c2w, c2b, s + OFF_POS2,
                                 s + OFF_X2, s + OFF_X2PO, L1_, L2_, 0);
    conv_k<<<dim3(4, 40), 256>>>(s + OFF_X2, c3w, c3b, s + OFF_POS3,
                                 nullptr, s + OFF_X3, L2_, L3_, 0);

    int M1 = B_ * L2_, M3 = B_ * L3_;
    gemm_k<<<dim3(5, (M1 + 63) / 64, 1), 256>>>(s + OFF_X2PO, 315, 0, 0, ain_w, 315, 0, 0,
        s + OFF_Q1, 315, 0, 0, ain_b, M1, 315, 315, 0, 1, 1);
    gemm_k<<<dim3(10, (M3 + 63) / 64, 1), 256>>>(s + OFF_X3, 315, 0, 0, ain_w + 315 * 315, 315, 0, 0,
        s + OFF_KV1, 630, 0, 0, ain_b + 315, M3, 630, 315, 0, 1, 1);
    gemm_k<<<dim3(4, 8, 24), 256>>>(
        s + OFF_Q1, 315, (long)L2_ * 315, 105,
        s + OFF_KV1, 630, (long)L3_ * 630, 105,
        s + OFF_P1, 255, (long)3 * L2_ * L3_, (long)L2_ * L3_,
        nullptr, L2_, L3_, 105, 1, 1, 3);
    softmax_k<<<(B_ * 3 * L2_ + 7) / 8, 256>>>(s + OFF_P1, B_ * 3 * L2_, L3_);
    gemm_k<<<dim3(2, 8, 24), 256>>>(
        s + OFF_P1, 255, (long)3 * L2_ * L3_, (long)L2_ * L3_,
        s + OFF_KV1 + 315, 630, (long)L3_ * 630, 105,
        s + OFF_O1, 315, (long)L2_ * 315, 105,
        nullptr, L2_, 105, L3_, 0, 0, 3);
    gemm_k<<<dim3(5, (M1 + 63) / 64, 1), 256>>>(s + OFF_O1, 315, 0, 0, aout_w, 315, 0, 0,
        s + OFF_X2A, 315, 0, 0, aout_b, M1, 315, 315, 0, 1, 1);

    int M0 = B_ * L1_;
    gemm_k<<<dim3(5, (M0 + 63) / 64, 1), 256>>>(s + OFF_X1PO, 315, 0, 0, ain_w, 315, 0, 0,
        s + OFF_Q2, 315, 0, 0, ain_b, M0, 315, 315, 0, 1, 1);
    gemm_k<<<dim3(10, (M1 + 63) / 64, 1), 256>>>(s + OFF_X2A, 315, 0, 0, ain_w + 315 * 315, 315, 0, 0,
        s + OFF_KV2, 630, 0, 0, ain_b + 315, M1, 630, 315, 0, 1, 1);
    gemm_k<<<dim3(8, 16, 24), 256>>>(
        s + OFF_Q2, 315, (long)L1_ * 315, 105,
        s + OFF_KV2, 630, (long)L2_ * 630, 105,
        s + OFF_P2, 511, (long)3 * L1_ * L2_, (long)L1_ * L2_,
        nullptr, L1_, L2_, 105, 1, 1, 3);
    softmax_k<<<(B_ * 3 * L1_ + 7) / 8, 256>>>(s + OFF_P2, B_ * 3 * L1_, L2_);
    gemm_k<<<dim3(2, 16, 24), 256>>>(
        s + OFF_P2, 511, (long)3 * L1_ * L2_, (long)L1_ * L2_,
        s + OFF_KV2 + 315, 630, (long)L2_ * 630, 105,
        s + OFF_O2, 315, (long)L1_ * 315, 105,
        nullptr, L1_, 105, L2_, 0, 0, 3);
    gemm_k<<<dim3(5, (M0 + 63) / 64, 1), 256>>>(s + OFF_O2, 315, 0, 0, aout_w, 315, 0, 0,
        s + OFF_X1A, 315, 0, 0, aout_b, M0, 315, 315, 0, 1, 1);

    gat_k<<<G_, 256>>>(s + OFF_X1A, e_index, e_attr,
                       gat_wl, gat_bl, gat_wr, gat_br, gat_we, gat_att, gat_bias,
                       s + OFF_XGRAPH);
    gemm_k<<<dim3(3, (G_ + 63) / 64, 1), 256>>>(s + OFF_XGRAPH, 32, 0, 0, gru_wih, 32, 0, 0,
        s + OFF_XGATES, 192, 0, 0, gru_bih, G_, 192, 32, 0, 1, 1);
    gru_k<<<B_, 192>>>(s + OFF_XGATES, gru_whh, gru_bhh, s + OFF_GRUOUT);
    cls_k<<<(G_ + 255) / 256, 256>>>(s + OFF_GRUOUT, fc1_w, fc1_b, fc2_w, fc2_b,
                                     s + OFF_SCORES);
    topk_k<<<24, 128>>>(s + OFF_SCORES, out);
}

// round 17
// speedup vs baseline: 1.0980x; 1.0980x over previous
#include <cuda_runtime.h>
#include <math.h>

#define B_    8
#define C_    63
#define S_    2048
#define F_    5
#define E_    315
#define L1_   1023
#define L2_   511
#define L3_   255
#define EPG_  504
#define G_    (B_*L1_)
#define NE_   ((long)G_*EPG_)
#define NEG_INF (-3.402823466e38f)
#define ACC_BIAS 128.0f

typedef unsigned long long ull;

constexpr long SZ_X1 = (long)B_*L1_*E_;
constexpr long SZ_X2 = (long)B_*L2_*E_;
constexpr long SZ_X3 = (long)B_*L3_*E_;
constexpr long OFF_X1     = 0;
constexpr long OFF_X1PO   = OFF_X1   + SZ_X1;
constexpr long OFF_X2     = OFF_X1PO + SZ_X1;
constexpr long OFF_X2PO   = OFF_X2   + SZ_X2;
constexpr long OFF_X3     = OFF_X2PO + SZ_X2;
constexpr long OFF_POS2   = OFF_X3   + SZ_X3;
constexpr long OFF_POS3   = OFF_POS2 + (long)L2_*C_;
constexpr long OFF_Q1     = OFF_POS3 + (long)L3_*C_;
constexpr long OFF_KV1    = OFF_Q1   + (long)B_*L2_*E_;
constexpr long OFF_P1     = OFF_KV1  + (long)B_*L3_*2*E_;
constexpr long OFF_O1     = OFF_P1   + (long)B_*3*L2_*L3_;
constexpr long OFF_X2A    = OFF_O1   + (long)B_*L2_*E_;
constexpr long OFF_Q2     = OFF_X2A  + (long)B_*L2_*E_;
constexpr long OFF_KV2    = OFF_Q2   + (long)B_*L1_*E_;
constexpr long OFF_P2     = OFF_KV2  + (long)B_*L2_*2*E_;
constexpr long OFF_O2     = OFF_P2   + (long)B_*3*L1_*L2_;
constexpr long OFF_X1A    = OFF_O2   + (long)B_*L1_*E_;
constexpr long OFF_XGRAPH = OFF_X1A  + (long)B_*L1_*E_;
constexpr long OFF_XGATES = OFF_XGRAPH + (long)G_*32;
constexpr long OFF_GRUOUT = OFF_XGATES + (long)G_*192;
constexpr long OFF_SCORES = OFF_GRUOUT + (long)G_*64;
constexpr long SCRATCH_TOTAL = OFF_SCORES + (long)G_*3;

__device__ float g_scratch[SCRATCH_TOTAL];

// ============ double-single (ds) fp32 library ============
struct dsf { float h, l; };
__device__ __forceinline__ dsf ds_two_sum(float a, float b) {
    float s = __fadd_rn(a, b);
    float bb = __fsub_rn(s, a);
    float err = __fadd_rn(__fsub_rn(a, __fsub_rn(s, bb)), __fsub_rn(b, bb));
    return {s, err};
}
__device__ __forceinline__ dsf ds_quick(float a, float b) {
    float s = __fadd_rn(a, b);
    return {s, __fsub_rn(b, __fsub_rn(s, a))};
}
__device__ __forceinline__ dsf ds_neg(dsf x) { return {-x.h, -x.l}; }
__device__ __forceinline__ dsf ds_add(dsf x, dsf y) {
    dsf t = ds_two_sum(x.h, y.h);
    t.l = __fadd_rn(t.l, __fadd_rn(x.l, y.l));
    return ds_quick(t.h, t.l);
}
__device__ __forceinline__ dsf ds_add_f(dsf x, float f) {
    dsf t = ds_two_sum(x.h, f);
    t.l = __fadd_rn(t.l, x.l);
    return ds_quick(t.h, t.l);
}
__device__ __forceinline__ dsf ds_mul(dsf x, dsf y) {
    float p = __fmul_rn(x.h, y.h);
    float e = __fmaf_rn(x.h, y.h, -p);
    e = __fmaf_rn(x.h, y.l, e);
    e = __fmaf_rn(x.l, y.h, e);
    return ds_quick(p, e);
}
__device__ __forceinline__ dsf ds_mul_f(dsf x, float f) {
    float p = __fmul_rn(x.h, f);
    float e = __fmaf_rn(x.h, f, -p);
    e = __fmaf_rn(x.l, f, e);
    return ds_quick(p, e);
}
__device__ __forceinline__ dsf ds_prod(float a, float b) {
    float p = __fmul_rn(a, b);
    return {p, __fmaf_rn(a, b, -p)};
}
__device__ __forceinline__ dsf ds_recip(dsf y) {
    float r0 = __frcp_rn(y.h);
    dsf om = ds_add_f(ds_neg(ds_mul_f(y, r0)), 1.0f);
    return ds_add_f(ds_mul_f(om, r0), r0);
}
__device__ __forceinline__ dsf ds_recip_f(float f) {
    float r0 = __frcp_rn(f);
    float t = __fmaf_rn(-f, r0, 1.0f);
    return ds_quick(r0, __fmul_rn(r0, t));
}
__device__ __forceinline__ void ds_mac_dsw(dsf& acc, float w, float hh, float hl) {
    float p = __fmul_rn(w, hh);
    float e = __fmaf_rn(w, hh, -p);
    e = __fmaf_rn(w, hl, e);
    dsf t = ds_two_sum(acc.h, p);
    acc.h = t.h;
    acc.l = __fadd_rn(acc.l, __fadd_rn(t.l, e));
}
__device__ __forceinline__ void ds_macf(dsf& acc, float a, float b) {
    float p = __fmul_rn(a, b);
    float e = __fmaf_rn(a, b, -p);
    dsf t = ds_two_sum(acc.h, p);
    acc.h = t.h;
    acc.l = __fadd_rn(acc.l, __fadd_rn(t.l, e));
}
constexpr double LN2D = 0.6931471805599453094172321214581766;
constexpr float EXP_C1 = 0.693359375f;
constexpr float EXP_C2 = (float)(LN2D - (double)EXP_C1);
constexpr float EXP_C3 = (float)(LN2D - (double)EXP_C1 - (double)EXP_C2);
constexpr float L2EF = 1.4426950408889634f;
constexpr float C6H = (float)(1.0/6.0),  C6L = (float)(1.0/6.0 - (double)C6H);
constexpr float C24H = (float)(1.0/24.0), C24L = (float)(1.0/24.0 - (double)C24H);
constexpr float I63H = (float)(1.0/63.0), I63L = (float)(1.0/63.0 - (double)I63H);
constexpr double ISCD = 0.09759000729485331905;
constexpr float ISCH = (float)ISCD, ISCL = (float)(ISCD - (double)ISCH);

__device__ __forceinline__ dsf ds_exp(dsf x) {
    if (x.h < -86.0f) return {0.f, 0.f};
    if (x.h >  86.0f) return {1e37f, 0.f};
    float nf = rintf(__fmul_rn(x.h, L2EF));
    float t1 = __fmaf_rn(-nf, EXP_C1, x.h);
    dsf p2 = ds_prod(nf, EXP_C2);
    dsf r = ds_two_sum(t1, -p2.h);
    r.l = __fadd_rn(r.l, __fadd_rn(x.l, __fadd_rn(-p2.l, __fmul_rn(-nf, EXP_C3))));
    r = ds_quick(r.h, r.l);
    dsf r2 = ds_mul(r, r);
    dsf r3 = ds_mul(r2, r);
    dsf r4 = ds_mul(r2, r2);
    float rf = r.h;
    float tail = __fmaf_rn(rf, 2.7557319e-7f, 2.7557319e-6f);
    tail = __fmaf_rn(rf, tail, 2.4801587e-5f);
    tail = __fmaf_rn(rf, tail, 1.9841270e-4f);
    tail = __fmaf_rn(rf, tail, 1.3888889e-3f);
    tail = __fmaf_rn(rf, tail, 8.3333333e-3f);
    float q = __fmul_rn(__fmul_rn(r4.h, rf), tail);
    dsf acc = ds_add(r, ds_mul_f(r2, 0.5f));
    acc = ds_add(acc, ds_mul(r3, dsf{C6H, C6L}));
    acc = ds_add(acc, ds_mul(r4, dsf{C24H, C24L}));
    acc = ds_add_f(acc, q);
    acc = ds_add_f(acc, 1.0f);
    float sc = __int_as_float(((int)nf + 127) << 23);
    return {__fmul_rn(acc.h, sc), __fmul_rn(acc.l, sc)};
}
__device__ __forceinline__ dsf ds_sigmoid(dsf x) {
    return ds_recip(ds_add_f(ds_exp(ds_neg(x)), 1.0f));
}
__device__ __forceinline__ dsf ds_tanh(dsf x) {
    dsf e = ds_exp(dsf{__fmul_rn(x.h, 2.f), __fmul_rn(x.l, 2.f)});
    return ds_mul(ds_add_f(e, -1.0f), ds_recip(ds_add_f(e, 1.0f)));
}

// ---------- packed f32x2 ----------
__device__ __forceinline__ ull f2x2_add(ull a, ull b) {
    ull r; asm("add.rn.f32x2 %0, %1, %2;" : "=l"(r) : "l"(a), "l"(b)); return r;
}
__device__ __forceinline__ ull f2x2_sub(ull a, ull b) {
    ull r; asm("sub.rn.f32x2 %0, %1, %2;" : "=l"(r) : "l"(a), "l"(b)); return r;
}
__device__ __forceinline__ ull f2x2_mul(ull a, ull b) {
    ull r; asm("mul.rn.f32x2 %0, %1, %2;" : "=l"(r) : "l"(a), "l"(b)); return r;
}
__device__ __forceinline__ ull f2x2_fma(ull a, ull b, ull c) {
    ull r; asm("fma.rn.f32x2 %0, %1, %2, %3;" : "=l"(r) : "l"(a), "l"(b), "l"(c)); return r;
}
__device__ __forceinline__ ull f2x2_neg(ull a) { return a ^ 0x8000000080000000ull; }
__device__ __forceinline__ ull f2x2_splat(float x) {
    ull r; asm("mov.b64 %0, {%1, %1};" : "=l"(r) : "f"(x)); return r;
}
__device__ __forceinline__ void f2x2_unpack(ull v, float& x, float& y) {
    asm("mov.b64 {%0, %1}, %2;" : "=f"(x), "=f"(y) : "l"(v));
}
// biased Fast2Sum ds MAC (hi pre-biased); nb = -b precomputed.
__device__ __forceinline__ void dsmac2(ull a, ull b, ull nb, ull& hi, ull& lo) {
    ull p   = f2x2_mul(a, b);
    ull em  = f2x2_fma(a, nb, p);
    ull s   = f2x2_add(hi, p);
    ull z   = f2x2_sub(s, hi);
    ull err = f2x2_sub(p, z);
    hi = s;
    lo = f2x2_add(lo, f2x2_sub(err, em));
}
__device__ __forceinline__ void dsmac2_dsh(ull w, ull nw, ull hh, ull hl, ull& hi, ull& lo) {
    ull p   = f2x2_mul(w, hh);
    ull em  = f2x2_fma(nw, hh, p);
    ull s   = f2x2_add(hi, p);
    ull z   = f2x2_sub(s, hi);
    ull err = f2x2_sub(p, z);
    hi = s;
    lo = f2x2_add(lo, f2x2_add(f2x2_sub(err, em), f2x2_mul(w, hl)));
}

// -------- adaptive avg pool --------
__global__ void pool_k(const float* __restrict__ in, float* __restrict__ out,
                       int Lin, int Lout) {
    int idx = blockIdx.x * blockDim.x + threadIdx.x;
    if (idx >= Lout * C_) return;
    int i = idx / C_, c = idx - C_ * i;
    int s = (i * Lin) / Lout;
    int e = ((i + 1) * Lin + Lout - 1) / Lout;
    double acc = 0.0;
    for (int l = s; l < e; l++) acc += (double)in[l * C_ + c];
    out[idx] = (float)(acc / (double)(e - s));
}

// -------- conv df64 + fused pos (single-sync double buffer) --------
__global__ __launch_bounds__(256, 3) void conv_k(
    const float* __restrict__ in, const float* __restrict__ W,
    const float* __restrict__ bias, const float* __restrict__ pos,
    float* __restrict__ outPre, float* __restrict__ outPost,
    int Lin, int Lout, int inOrig) {
    int l0 = blockIdx.x * 64;
    int bf = blockIdx.y;
    int b = bf / F_, f = bf - b * F_;
    __shared__ __align__(16) float As[2][16][68];
    __shared__ __align__(16) float Bs[2][16][68];
    int tid = threadIdx.x;
    int tx = tid & 15, ty = tid >> 4;
    const ull bias2 = f2x2_splat(ACC_BIAS);
    ull hi2[4][2], lo2[4][2];
#pragma unroll
    for (int i = 0; i < 4; i++)
#pragma unroll
        for (int jp = 0; jp < 2; jp++) { hi2[i][jp] = bias2; lo2[i][jp] = 0ull; }
    const int akk = tid & 15, amb = tid >> 4;
    const int bn = tid & 63, bkb = tid >> 6;
    float ra[4], rb[4];
    auto loadA = [&](int k0) {
        int kidx = k0 + akk;
#pragma unroll
        for (int q = 0; q < 4; q++) {
            int co = amb + q * 16;
            ra[q] = (co < 63 && kidx < 189) ? W[co * 189 + kidx] : 0.f;
        }
    };
    auto loadB = [&](int k0) {
        int gl = l0 + bn;
#pragma unroll
        for (int q = 0; q < 4; q++) {
            int kidx = k0 + bkb + q * 4;
            float v = 0.f;
            if (kidx < 189 && gl < Lout) {
                int ci = kidx / 3, kx = kidx - ci * 3;
                int si = 2 * gl + kx;
                v = inOrig ? in[((long)(b * 63 + ci) * Lin + si) * 5 + f]
                           : in[((long)b * Lin + si) * 315 + f * 63 + ci];
            }
            rb[q] = v;
        }
    };
    loadA(0); loadB(0);
    int buf = 0;
    for (int k0 = 0; k0 < 192; k0 += 16) {
#pragma unroll
        for (int q = 0; q < 4; q++) As[buf][akk][amb + q * 16] = ra[q];
#pragma unroll
        for (int q = 0; q < 4; q++) Bs[buf][bkb + q * 4][bn] = rb[q];
        __syncthreads();
        if (k0 + 16 < 192) { loadA(k0 + 16); loadB(k0 + 16); }
#pragma unroll
        for (int kk = 0; kk < 16; kk++) {
            float4 a4 = *(const float4*)&As[buf][kk][ty * 4];
            ulonglong2 bq = *(const ulonglong2*)&Bs[buf][kk][tx * 4];
            ull b2[2] = {bq.x, bq.y};
            ull nb2[2] = {f2x2_neg(bq.x), f2x2_neg(bq.y)};
            ull a2[4] = {f2x2_splat(a4.x), f2x2_splat(a4.y),
                         f2x2_splat(a4.z), f2x2_splat(a4.w)};
#pragma unroll
            for (int i = 0; i < 4; i++)
#pragma unroll
                for (int jp = 0; jp < 2; jp++)
                    dsmac2(a2[i], b2[jp], nb2[jp], hi2[i][jp], lo2[i][jp]);
        }
        buf ^= 1;
    }
#pragma unroll
    for (int i = 0; i < 4; i++) {
        int co = ty * 4 + i;
        if (co >= 63) continue;
#pragma unroll
        for (int jp = 0; jp < 2; jp++) {
            float h0, h1, l0f, l1f;
            f2x2_unpack(hi2[i][jp], h0, h1);
            f2x2_unpack(lo2[i][jp], l0f, l1f);
            float hv[2] = {__fsub_rn(h0, ACC_BIAS), __fsub_rn(h1, ACC_BIAS)};
            float lv[2] = {l0f, l1f};
#pragma unroll
            for (int u = 0; u < 2; u++) {
                int l = l0 + tx * 4 + jp * 2 + u;
                if (l >= Lout) continue;
                dsf sum = ds_two_sum(hv[u], lv[u]);
                float vpre = ds_add_f(sum, bias[co]).h;
                long oidx = ((long)b * Lout + l) * 315 + f * 63 + co;
                if (outPre)  outPre[oidx] = vpre;
                if (outPost) outPost[oidx] = __fadd_rn(vpre, pos[l * 63 + co]);
            }
        }
    }
}

// -------- generic GEMM df64, 64x64 tile --------
__global__ __launch_bounds__(256, 3) void gemm_k(
    const float* __restrict__ A, int lda, long sAo, long sAi,
    const float* __restrict__ Bm, int ldb, long sBo, long sBi,
    float* __restrict__ Cm, int ldc, long sCo, long sCi,
    const float* __restrict__ bias,
    int M, int N, int K, int scaleIsc, int transB, int nInner) {
    int z = blockIdx.z;
    int zo = z / nInner, zi = z - zo * nInner;
    A += zo * sAo + zi * sAi;
    Bm += zo * sBo + zi * sBi;
    Cm += zo * sCo + zi * sCi;
    __shared__ __align__(16) float As[2][16][68];
    __shared__ __align__(16) float Bs[2][16][68];
    int m0 = blockIdx.y * 64, n0 = blockIdx.x * 64;
    int tid = threadIdx.x;
    int tx = tid & 15, ty = tid >> 4;
    const ull bias2 = f2x2_splat(ACC_BIAS);
    ull hi2[4][2], lo2[4][2];
#pragma unroll
    for (int i = 0; i < 4; i++)
#pragma unroll
        for (int jp = 0; jp < 2; jp++) { hi2[i][jp] = bias2; lo2[i][jp] = 0ull; }
    const int akk = tid & 15, amb = tid >> 4;
    const int bn = tid & 63, bkb = tid >> 6;
    float ra[4], rb[4];
    auto loadA = [&](int k0) {
        int gk = k0 + akk;
        bool kok = gk < K;
#pragma unroll
        for (int q = 0; q < 4; q++) {
            int gm = m0 + amb + q * 16;
            ra[q] = (gm < M && kok) ? A[(long)gm * lda + gk] : 0.f;
        }
    };
    auto loadB = [&](int k0) {
        if (transB) {
            int gk = k0 + akk;
            bool kok = gk < K;
#pragma unroll
            for (int q = 0; q < 4; q++) {
                int gn = n0 + amb + q * 16;
                rb[q] = (gn < N && kok) ? Bm[(long)gn * ldb + gk] : 0.f;
            }
        } else {
            int gn = n0 + bn;
            bool nok = gn < N;
#pragma unroll
            for (int q = 0; q < 4; q++) {
                int gk = k0 + bkb + q * 4;
                rb[q] = (nok && gk < K) ? Bm[(long)gk * ldb + gn] : 0.f;
            }
        }
    };
    loadA(0); loadB(0);
    int buf = 0;
    for (int k0 = 0; k0 < K; k0 += 16) {
#pragma unroll
        for (int q = 0; q < 4; q++) As[buf][akk][amb + q * 16] = ra[q];
        if (transB) {
#pragma unroll
            for (int q = 0; q < 4; q++) Bs[buf][akk][amb + q * 16] = rb[q];
        } else {
#pragma unroll
            for (int q = 0; q < 4; q++) Bs[buf][bkb + q * 4][bn] = rb[q];
        }
        __syncthreads();
        if (k0 + 16 < K) { loadA(k0 + 16); loadB(k0 + 16); }
#pragma unroll
        for (int kk = 0; kk < 16; kk++) {
            float4 a4 = *(const float4*)&As[buf][kk][ty * 4];
            ulonglong2 bq = *(const ulonglong2*)&Bs[buf][kk][tx * 4];
            ull b2[2] = {bq.x, bq.y};
            ull nb2[2] = {f2x2_neg(bq.x), f2x2_neg(bq.y)};
            ull a2[4] = {f2x2_splat(a4.x), f2x2_splat(a4.y),
                         f2x2_splat(a4.z), f2x2_splat(a4.w)};
#pragma unroll
            for (int i = 0; i < 4; i++)
#pragma unroll
                for (int jp = 0; jp < 2; jp++)
                    dsmac2(a2[i], b2[jp], nb2[jp], hi2[i][jp], lo2[i][jp]);
        }
        buf ^= 1;
    }
#pragma unroll
    for (int i = 0; i < 4; i++) {
        int gm = m0 + ty * 4 + i;
        if (gm >= M) continue;
#pragma unroll
        for (int jp = 0; jp < 2; jp++) {
            float h0, h1, l0f, l1f;
            f2x2_unpack(hi2[i][jp], h0, h1);
            f2x2_unpack(lo2[i][jp], l0f, l1f);
            float hv[2] = {__fsub_rn(h0, ACC_BIAS), __fsub_rn(h1, ACC_BIAS)};
            float lv[2] = {l0f, l1f};
#pragma unroll
            for (int u = 0; u < 2; u++) {
                int gn = n0 + tx * 4 + jp * 2 + u;
                if (gn >= N) continue;
                dsf v = ds_two_sum(hv[u], lv[u]);
                if (scaleIsc) v = ds_mul(v, dsf{ISCH, ISCL});
                if (bias) v = ds_add_f(v, bias[gn]);
                Cm[(long)gm * ldc + gn] = v.h;
            }
        }
    }
}

// -------- softmax, ds exp --------
__global__ void softmax_k(float* __restrict__ P, int rows, int Ld) {
    int warp = (blockIdx.x * blockDim.x + threadIdx.x) >> 5;
    int lane = threadIdx.x & 31;
    if (warp >= rows) return;
    float* p = P + (long)warp * Ld;
    float v[16];
    float m = NEG_INF;
#pragma unroll
    for (int q = 0; q < 16; q++) {
        int i = lane + (q << 5);
        v[q] = (i < Ld) ? p[i] : NEG_INF;
        m = fmaxf(m, v[q]);
    }
#pragma unroll
    for (int off = 16; off; off >>= 1) m = fmaxf(m, __shfl_xor_sync(0xffffffffu, m, off));
    dsf ex[16];
    dsf s = {0.f, 0.f};
#pragma unroll
    for (int q = 0; q < 16; q++) {
        int i = lane + (q << 5);
        ex[q] = (i < Ld) ? ds_exp(ds_two_sum(v[q], -m)) : dsf{0.f, 0.f};
        s = ds_add(s, ex[q]);
    }
#pragma unroll
    for (int off = 16; off; off >>= 1) {
        dsf o = {__shfl_xor_sync(0xffffffffu, s.h, off),
                 __shfl_xor_sync(0xffffffffu, s.l, off)};
        s = ds_add(s, o);
    }
    dsf inv = ds_recip(s);
#pragma unroll
    for (int q = 0; q < 16; q++) {
        int i = lane + (q << 5);
        if (i < Ld) p[i] = ds_mul(ex[q], inv).h;
    }
}

// -------- GATv2 per graph --------
__global__ __launch_bounds__(256) void gat_k(
    const float* __restrict__ xfeat, const int* __restrict__ edge_index,
    const float* __restrict__ edge_attr,
    const float* __restrict__ wl, const float* __restrict__ blv,
    const float* __restrict__ wr, const float* __restrict__ brv,
    const float* __restrict__ wev, const float* __restrict__ attv,
    const float* __restrict__ gbias, float* __restrict__ xgraph) {
    int g = blockIdx.x;
    int tid = threadIdx.x;
    int warp = tid >> 5, lane = tid & 31;
    __shared__ float xn[E_];
    __shared__ float xl[63 * 33], xr[63 * 33];
    __shared__ float eav[EPG_];
    __shared__ short srcl[EPG_], dstl[EPG_], sorted_[EPG_];
    __shared__ int deg[63], start_[64], fill[63];
    __shared__ float lah[63], lal[63];
    __shared__ float sch[EPG_ + 63], scl[EPG_ + 63];
    __shared__ float2 outrow[2016];
    __shared__ float wls[160], wrs[160], wes[32], atts[32];

    const long ebase = (long)g * EPG_;
    for (int i = tid; i < E_; i += 256) xn[i] = xfeat[(long)g * E_ + i];
    if (tid < 160) { wls[tid] = wl[tid]; wrs[tid] = wr[tid]; }
    if (tid < 32)  { wes[tid] = wev[tid]; atts[tid] = attv[tid]; }
    if (tid < 63)  { deg[tid] = 0; fill[tid] = 0; }
    for (int e = tid; e < EPG_; e += 256) {
        srcl[e] = (short)(edge_index[ebase + e] - g * 63);
        dstl[e] = (short)(edge_index[NE_ + ebase + e] - g * 63);
        eav[e]  = edge_attr[ebase + e];
    }
    __syncthreads();
    for (int i = tid; i < 2016; i += 256) {
        int nd = i >> 5, k = i & 31;
        const float* xv = &xn[nd * 5];
        dsf sl = {blv[k], 0.f}, sr = {brv[k], 0.f};
#pragma unroll
        for (int f = 0; f < 5; f++) {
            ds_macf(sl, wls[k * 5 + f], xv[f]);
            ds_macf(sr, wrs[k * 5 + f], xv[f]);
        }
        xl[nd * 33 + k] = __fadd_rn(sl.h, sl.l);
        xr[nd * 33 + k] = __fadd_rn(sr.h, sr.l);
    }
    for (int e = tid; e < EPG_; e += 256) atomicAdd(&deg[dstl[e]], 1);
    __syncthreads();
    if (tid == 0) {
        int a = 0;
        for (int d = 0; d < 63; d++) { start_[d] = a; a += deg[d]; }
        start_[63] = a;
    }
    __syncthreads();
    for (int e = tid; e < EPG_; e += 256) {
        int d = dstl[e];
        int p = start_[d] + atomicAdd(&fill[d], 1);
        sorted_[p] = (short)e;
    }
    __syncthreads();
    if (tid < 63) {
        int s0 = start_[tid], cnt = deg[tid];
        dsf la = {0.f, 0.f};
        for (int j = 0; j < cnt; j++) la = ds_add_f(la, eav[sorted_[s0 + j]]);
        la = ds_mul(la, ds_recip_f((float)(cnt > 0 ? cnt : 1)));
        lah[tid] = la.h; lal[tid] = la.l;
    }
    __syncthreads();
    for (int i = tid; i < EPG_ + 63; i += 256) {
        int src, d;
        dsf sco = {0.f, 0.f};
        if (i < EPG_) {
            int e = sorted_[i];
            src = srcl[e]; d = dstl[e];
            float ea = eav[e];
#pragma unroll
            for (int k = 0; k < 32; k++) {
                dsf m = ds_add(ds_two_sum(xl[src * 33 + k], xr[d * 33 + k]),
                               ds_prod(wes[k], ea));
                if (m.h < 0.f) m = ds_mul_f(m, 0.2f);
                ds_mac_dsw(sco, atts[k], m.h, m.l);
            }
        } else {
            d = i - EPG_; src = d;
            dsf la = {lah[d], lal[d]};
#pragma unroll
            for (int k = 0; k < 32; k++) {
                dsf m = ds_add(ds_two_sum(xl[d * 33 + k], xr[d * 33 + k]),
                               ds_mul_f(la, wes[k]));
                if (m.h < 0.f) m = ds_mul_f(m, 0.2f);
                ds_mac_dsw(sco, atts[k], m.h, m.l);
            }
        }
        dsf sn = ds_two_sum(sco.h, sco.l);
        sch[i] = sn.h; scl[i] = sn.l;
    }
    __syncthreads();
    for (int d = warp; d < 63; d += 8) {
        int s0 = start_[d];
        int cnt = deg[d];
        dsf mx = {NEG_INF, 0.f};
        for (int j = lane; j <= cnt; j += 32) {
            int slot = (j < cnt) ? (s0 + j) : (EPG_ + d);
            dsf sv = {sch[slot], scl[slot]};
            if (sv.h > mx.h) mx = sv;
        }
#pragma unroll
        for (int off = 16; off; off >>= 1) {
            float oh = __shfl_xor_sync(0xffffffffu, mx.h, off);
            float ol = __shfl_xor_sync(0xffffffffu, mx.l, off);
            if (oh > mx.h) { mx.h = oh; mx.l = ol; }
        }
        dsf ssum = {0.f, 0.f};
        for (int j = lane; j <= cnt; j += 32) {
            int slot = (j < cnt) ? (s0 + j) : (EPG_ + d);
            dsf ex = ds_exp(ds_add(dsf{sch[slot], scl[slot]}, ds_neg(mx)));
            sch[slot] = ex.h; scl[slot] = ex.l;
            ssum = ds_add(ssum, ex);
        }
#pragma unroll
        for (int off = 16; off; off >>= 1) {
            dsf o = {__shfl_xor_sync(0xffffffffu, ssum.h, off),
                     __shfl_xor_sync(0xffffffffu, ssum.l, off)};
            ssum = ds_add(ssum, o);
        }
        __syncwarp();
        dsf acc = {0.f, 0.f};
        for (int j = 0; j <= cnt; j++) {
            int slot, src;
            if (j < cnt) { slot = s0 + j; src = srcl[sorted_[slot]]; }
            else { slot = EPG_ + d; src = d; }
            acc = ds_add(acc, ds_mul_f(dsf{sch[slot], scl[slot]}, xl[src * 33 + lane]));
        }
        dsf o = ds_mul(acc, ds_recip(ssum));
        outrow[d * 32 + lane] = make_float2(o.h, o.l);
        __syncwarp();
    }
    __syncthreads();
    if (tid < 32) {
        dsf s = {0.f, 0.f};
        for (int d = 0; d < 63; d++) {
            float2 v = outrow[d * 32 + tid];
            s = ds_add(s, dsf{v.x, v.y});
        }
        s = ds_mul(s, dsf{I63H, I63L});
        xgraph[(long)g * 32 + tid] = ds_add_f(s, gbias[tid]).h;
    }
}

// -------- GRU scan: xgates register-prefetch, 2 syncs/step --------
__global__ __launch_bounds__(192) void gru_k(
    const float* __restrict__ xgates, const float* __restrict__ whh,
    const float* __restrict__ bhh, float* __restrict__ gruout) {
    int b = blockIdx.x;
    int t = threadIdx.x;
    __shared__ __align__(8) float hsh[64], hsl[64];
    __shared__ float hgh[64], hgl[64];
    __shared__ float rzh[128], rzl[128];
    ull w2[32], nw2[32];
#pragma unroll
    for (int j = 0; j < 32; j++) {
        float w0 = whh[t * 64 + 2 * j], w1 = whh[t * 64 + 2 * j + 1];
        ull r; asm("mov.b64 %0, {%1, %2};" : "=l"(r) : "f"(w0), "f"(w1));
        w2[j] = r;
        nw2[j] = f2x2_neg(r);
    }
    float bh = bhh[t];
    const ull bias2 = f2x2_splat(ACC_BIAS);
    if (t < 64) { hsh[t] = 0.f; hsl[t] = 0.f; }
    const float* xgb = xgates + (long)b * L1_ * 192;
    // prefetch step 0 gates
    float xga = (t < 128) ? xgb[t] : 0.f;
    float xgn = (t < 64) ? xgb[128 + t] : 0.f;
    __syncthreads();
    for (int l = 0; l < L1_; l++) {
        // issue next step's gate loads early (h-independent, hidden behind dot)
        float nxa = 0.f, nxn = 0.f;
        if (l + 1 < L1_) {
            const float* xgn1 = xgb + (long)(l + 1) * 192;
            if (t < 128) nxa = xgn1[t];
            if (t < 64)  nxn = xgn1[128 + t];
        }
        ull hiA = bias2, loA = 0ull, hiB = bias2, loB = 0ull;
#pragma unroll
        for (int j = 0; j < 32; j += 2) {
            ull hhA = *(const ull*)&hsh[2 * j];
            ull hlA = *(const ull*)&hsl[2 * j];
            dsmac2_dsh(w2[j], nw2[j], hhA, hlA, hiA, loA);
            ull hhB = *(const ull*)&hsh[2 * j + 2];
            ull hlB = *(const ull*)&hsl[2 * j + 2];
            dsmac2_dsh(w2[j + 1], nw2[j + 1], hhB, hlB, hiB, loB);
        }
        float a0, a1, b0, b1, c0, c1, d0, d1;
        f2x2_unpack(hiA, a0, a1); f2x2_unpack(loA, c0, c1);
        f2x2_unpack(hiB, b0, b1); f2x2_unpack(loB, d0, d1);
        a0 = __fsub_rn(a0, ACC_BIAS); a1 = __fsub_rn(a1, ACC_BIAS);
        b0 = __fsub_rn(b0, ACC_BIAS); b1 = __fsub_rn(b1, ACC_BIAS);
        dsf hg = ds_add(ds_add(dsf{a0, c0}, dsf{a1, c1}),
                        ds_add(dsf{b0, d0}, dsf{b1, d1}));
        hg = ds_add_f(hg, bh);
        if (t < 128) {
            dsf v = ds_sigmoid(ds_add_f(hg, xga));
            rzh[t] = v.h; rzl[t] = v.l;
        } else {
            hgh[t - 128] = hg.h; hgl[t - 128] = hg.l;
        }
        __syncthreads();
        if (t < 64) {
            dsf r = {rzh[t], rzl[t]};
            dsf z = {rzh[64 + t], rzl[64 + t]};
            dsf n = ds_tanh(ds_add_f(ds_mul(r, dsf{hgh[t], hgl[t]}), xgn));
            dsf h = {hsh[t], hsl[t]};
            dsf hnew = ds_add(ds_mul(ds_add_f(ds_neg(z), 1.0f), n), ds_mul(z, h));
            hsh[t] = hnew.h; hsl[t] = hnew.l;
            gruout[((long)b * L1_ + l) * 64 + t] = hnew.h;
        }
        xga = nxa; xgn = nxn;
        __syncthreads();
    }
}

// -------- classifier --------
__global__ __launch_bounds__(256) void cls_k(
    const float* __restrict__ gru, const float* __restrict__ w1,
    const float* __restrict__ b1, const float* __restrict__ w2,
    const float* __restrict__ b2, float* __restrict__ sc) {
    __shared__ float s1[2048], s2[96], sb1[32], sb2[3];
    int t = threadIdx.x;
    for (int i = t; i < 2048; i += 256) s1[i] = w1[i];
    if (t < 96) s2[t] = w2[t];
    if (t < 32) sb1[t] = b1[t];
    if (t < 3)  sb2[t] = b2[t];
    __syncthreads();
    int g = blockIdx.x * 256 + t;
    if (g >= G_) return;
    float h[64];
    const float* gr = gru + (long)g * 64;
#pragma unroll
    for (int j = 0; j < 64; j++) h[j] = gr[j];
    dsf o0 = {sb2[0], 0.f}, o1 = {sb2[1], 0.f}, o2 = {sb2[2], 0.f};
    for (int u = 0; u < 32; u++) {
        dsf a = {sb1[u], 0.f};
#pragma unroll
        for (int j = 0; j < 64; j++) ds_macf(a, s1[u * 64 + j], h[j]);
        if (a.h < 0.f) { a.h = 0.f; a.l = 0.f; }
        ds_mac_dsw(o0, s2[u], a.h, a.l);
        ds_mac_dsw(o1, s2[32 + u], a.h, a.l);
        ds_mac_dsw(o2, s2[64 + u], a.h, a.l);
    }
    sc[(long)g * 3 + 0] = __fadd_rn(o0.h, o0.l);
    sc[(long)g * 3 + 1] = __fadd_rn(o1.h, o1.l);
    sc[(long)g * 3 + 2] = __fadd_rn(o2.h, o2.l);
}

// -------- top-5 --------
__global__ __launch_bounds__(128) void topk_k(const float* __restrict__ scores,
                                              float* __restrict__ out) {
    int bc = blockIdx.x;
    int b = bc / 3, c = bc - 3 * b;
    __shared__ float sv[L1_];
    __shared__ float bval[128];
    __shared__ int bidx[128];
    __shared__ float ssum;
    int t = threadIdx.x;
    for (int i = t; i < L1_; i += 128) sv[i] = scores[((long)b * L1_ + i) * 3 + c];
    if (t == 0) ssum = 0.f;
    __syncthreads();
    for (int k = 0; k < 5; k++) {
        float mv = NEG_INF; int mi = 0x7fffffff;
        for (int i = t; i < L1_; i += 128) {
            float v = sv[i];
            if (v > mv) { mv = v; mi = i; }
        }
        bval[t] = mv; bidx[t] = mi;
        __syncthreads();
        for (int off = 64; off; off >>= 1) {
            if (t < off) {
                if (bval[t + off] > bval[t] ||
                    (bval[t + off] == bval[t] && bidx[t + off] < bidx[t])) {
                    bval[t] = bval[t + off]; bidx[t] = bidx[t + off];
                }
            }
            __syncthreads();
        }
        if (t == 0) {
            out[24 + (b * 5 + k) * 3 + c] = (float)bidx[0];
            ssum += bval[0];
            sv[bidx[0]] = NEG_INF;
        }
        __syncthreads();
    }
    if (t == 0) out[b * 3 + c] = ssum * 0.2f;
}

extern "C" void kernel_launch(void* const* d_in, const int* in_sizes, int n_in,
                              void* d_out, int out_size) {
    const float* x        = (const float*)d_in[0];
    const float* c1w      = (const float*)d_in[1];
    const float* c1b      = (const float*)d_in[2];
    const float* c2w      = (const float*)d_in[3];
    const float* c2b      = (const float*)d_in[4];
    const float* c3w      = (const float*)d_in[5];
    const float* c3b      = (const float*)d_in[6];
    const float* pos_emb  = (const float*)d_in[7];
    const float* ain_w    = (const float*)d_in[8];
    const float* ain_b    = (const float*)d_in[9];
    const float* aout_w   = (const float*)d_in[10];
    const float* aout_b   = (const float*)d_in[11];
    const float* gat_wl   = (const float*)d_in[12];
    const float* gat_bl   = (const float*)d_in[13];
    const float* gat_wr   = (const float*)d_in[14];
    const float* gat_br   = (const float*)d_in[15];
    const float* gat_we   = (const float*)d_in[16];
    const float* gat_att  = (const float*)d_in[17];
    const float* gat_bias = (const float*)d_in[18];
    const float* gru_wih  = (const float*)d_in[19];
    const float* gru_whh  = (const float*)d_in[20];
    const float* gru_bih  = (const float*)d_in[21];
    const float* gru_bhh  = (const float*)d_in[22];
    const float* fc1_w    = (const float*)d_in[23];
    const float* fc1_b    = (const float*)d_in[24];
    const float* fc2_w    = (const float*)d_in[25];
    const float* fc2_b    = (const float*)d_in[26];
    const float* e_attr   = (const float*)d_in[27];
    const int*   e_index  = (const int*)d_in[28];
    float* out = (float*)d_out;

    float* s;
    cudaGetSymbolAddress((void**)&s, g_scratch);

    pool_k<<<(L2_ * C_ + 255) / 256, 256>>>(pos_emb, s + OFF_POS2, L1_, L2_);
    pool_k<<<(L3_ * C_ + 255) / 256, 256>>>(s + OFF_POS2, s + OFF_POS3, L2_, L3_);
    conv_k<<<dim3(16, 40), 256>>>(x, c1w, c1b, pos_emb,
                                  s + OFF_X1, s + OFF_X1PO, S_, L1_, 1);
    conv_k<<<dim3(8, 40), 256>>>(s + OFF_X1, c2w, c2b, s + OFF_POS2,
                                 s + OFF_X2, s + OFF_X2PO, L1_, L2_, 0);
    conv_k<<<dim3(4, 40), 256>>>(s + OFF_X2, c3w, c3b, s + OFF_POS3,
                                 nullptr, s + OFF_X3, L2_, L3_, 0);

    int M1 = B_ * L2_, M3 = B_ * L3_;
    gemm_k<<<dim3(5, (M1 + 63) / 64, 1), 256>>>(s + OFF_X2PO, 315, 0, 0, ain_w, 315, 0, 0,
        s + OFF_Q1, 315, 0, 0, ain_b, M1, 315, 315, 0, 1, 1);
    gemm_k<<<dim3(10, (M3 + 63) / 64, 1), 256>>>(s + OFF_X3, 315, 0, 0, ain_w + 315 * 315, 315, 0, 0,
        s + OFF_KV1, 630, 0, 0, ain_b + 315, M3, 630, 315, 0, 1, 1);
    gemm_k<<<dim3(4, 8, 24), 256>>>(
        s + OFF_Q1, 315, (long)L2_ * 315, 105,
        s + OFF_KV1, 630, (long)L3_ * 630, 105,
        s + OFF_P1, 255, (long)3 * L2_ * L3_, (long)L2_ * L3_,
        nullptr, L2_, L3_, 105, 1, 1, 3);
    softmax_k<<<(B_ * 3 * L2_ + 7) / 8, 256>>>(s + OFF_P1, B_ * 3 * L2_, L3_);
    gemm_k<<<dim3(2, 8, 24), 256>>>(
        s + OFF_P1, 255, (long)3 * L2_ * L3_, (long)L2_ * L3_,
        s + OFF_KV1 + 315, 630, (long)L3_ * 630, 105,
        s + OFF_O1, 315, (long)L2_ * 315, 105,
        nullptr, L2_, 105, L3_, 0, 0, 3);
    gemm_k<<<dim3(5, (M1 + 63) / 64, 1), 256>>>(s + OFF_O1, 315, 0, 0, aout_w, 315, 0, 0,
        s + OFF_X2A, 315, 0, 0, aout_b, M1, 315, 315, 0, 1, 1);

    int M0 = B_ * L1_;
    gemm_k<<<dim3(5, (M0 + 63) / 64, 1), 256>>>(s + OFF_X1PO, 315, 0, 0, ain_w, 315, 0, 0,
        s + OFF_Q2, 315, 0, 0, ain_b, M0, 315, 315, 0, 1, 1);
    gemm_k<<<dim3(10, (M1 + 63) / 64, 1), 256>>>(s + OFF_X2A, 315, 0, 0, ain_w + 315 * 315, 315, 0, 0,
        s + OFF_KV2, 630, 0, 0, ain_b + 315, M1, 630, 315, 0, 1, 1);
    gemm_k<<<dim3(8, 16, 24), 256>>>(
        s + OFF_Q2, 315, (long)L1_ * 315, 105,
        s + OFF_KV2, 630, (long)L2_ * 630, 105,
        s + OFF_P2, 511, (long)3 * L1_ * L2_, (long)L1_ * L2_,
        nullptr, L1_, L2_, 105, 1, 1, 3);
    softmax_k<<<(B_ * 3 * L1_ + 7) / 8, 256>>>(s + OFF_P2, B_ * 3 * L1_, L2_);
    gemm_k<<<dim3(2, 16, 24), 256>>>(
        s + OFF_P2, 511, (long)3 * L1_ * L2_, (long)L1_ * L2_,
        s + OFF_KV2 + 315, 630, (long)L2_ * 630, 105,
        s + OFF_O2, 315, (long)L1_ * 315, 105,
        nullptr, L1_, 105, L2_, 0, 0, 3);
    gemm_k<<<dim3(5, (M0 + 63) / 64, 1), 256>>>(s + OFF_O2, 315, 0, 0, aout_w, 315, 0, 0,
        s + OFF_X1A, 315, 0, 0, aout_b, M0, 315, 315, 0, 1, 1);

    gat_k<<<G_, 256>>>(s + OFF_X1A, e_index, e_attr,
                       gat_wl, gat_bl, gat_wr, gat_br, gat_we, gat_att, gat_bias,
                       s + OFF_XGRAPH);
    gemm_k<<<dim3(3, (G_ + 63) / 64, 1), 256>>>(s + OFF_XGRAPH, 32, 0, 0, gru_wih, 32, 0, 0,
        s + OFF_XGATES, 192, 0, 0, gru_bih, G_, 192, 32, 0, 1, 1);
    gru_k<<<B_, 192>>>(s + OFF_XGATES, gru_whh, gru_bhh, s + OFF_GRUOUT);
    cls_k<<<(G_ + 255) / 256, 256>>>(s + OFF_GRUOUT, fc1_w, fc1_b, fc2_w, fc2_b,
                                     s + OFF_SCORES);
    topk_k<<<24, 128>>>(s + OFF_SCORES, out);
}